// round 12
// baseline (speedup 1.0000x reference)
#include <cuda_runtime.h>
#include <cuda_bf16.h>
#include <math.h>
#include <stdint.h>

// ---------------- problem constants ----------------
#define NN      100000      // nodes
#define NPAD    100096      // padded to 782*128
#define EE      1600000     // edges
#define GG      4096        // graphs
#define NLAYER  4           // 1 input conv + 3 blocks

// ---------------- static scratch (no allocations allowed) ----------------
__device__ float g_h0[(size_t)NPAD * 128];      // ping
__device__ float g_h1[(size_t)NPAD * 128];      // pong
__device__ float g_qkvs[(size_t)NPAD * 512];    // [q|..|..|s] per node (fp32; k/v cols dead)
__device__ __nv_bfloat16 g_kv[(size_t)NPAD * 256]; // packed [k(128)|v(128)] bf16 per node
__device__ int   g_deg[NN];
__device__ int   g_rowptr[NN + 1];
__device__ int   g_cursor[NN];
__device__ int   g_src[EE];                     // src node per CSR slot (sorted by dst)
__device__ float g_pool[GG * 128];
__device__ float g_cnt[GG];
// split-bf16 weights: [layer][hi|lo][512 n][128 k] halves  (n-major, k-contiguous)
__device__ __nv_bfloat16 g_wtb[(size_t)NLAYER * 2 * 512 * 128];

struct AllW {
    const float* W[16];   // [layer*4 + {q,k,v,s}] each 128x128 row-major (in,out)
    const float* b[16];
};

// ---------------- utility kernels ----------------
__global__ void k_zero() {
    int i = blockIdx.x * blockDim.x + threadIdx.x;
    if (i < NN) g_deg[i] = 0;
    if (i < GG * 128) g_pool[i] = 0.f;
    if (i < GG) g_cnt[i] = 0.f;
}

__global__ void k_copy_x(const float* __restrict__ x) {
    int i = blockIdx.x * blockDim.x + threadIdx.x;   // float4 index
    if (i < NN * 32) {
        reinterpret_cast<float4*>(g_h0)[i] = reinterpret_cast<const float4*>(x)[i];
    }
}

__global__ void k_count(const int* __restrict__ ei) {
    int e = blockIdx.x * blockDim.x + threadIdx.x;
    if (e < EE) atomicAdd(&g_deg[ei[EE + e]], 1);
}

__global__ void k_scan() {
    __shared__ int ssum[1024];
    int t = threadIdx.x;
    const int per = (NN + 1023) >> 10;
    int lo = t * per;
    int hi = lo + per; if (hi > NN) hi = NN;
    if (lo > NN) lo = NN;
    int s = 0;
    for (int i = lo; i < hi; ++i) s += g_deg[i];
    ssum[t] = s;
    __syncthreads();
    for (int off = 1; off < 1024; off <<= 1) {
        int v = (t >= off) ? ssum[t - off] : 0;
        __syncthreads();
        ssum[t] += v;
        __syncthreads();
    }
    int run = (t == 0) ? 0 : ssum[t - 1];
    for (int i = lo; i < hi; ++i) {
        g_rowptr[i] = run;
        g_cursor[i] = run;
        run += g_deg[i];
    }
    if (t == 1023) g_rowptr[NN] = run;
}

__global__ void k_scatter(const int* __restrict__ ei) {
    int e = blockIdx.x * blockDim.x + threadIdx.x;
    if (e < EE) {
        int s = ei[e];
        int d = ei[EE + e];
        int slot = atomicAdd(&g_cursor[d], 1);
        g_src[slot] = s;
    }
}

// ---------------- weight prepass: transpose + split-bf16 ----------------
__global__ void k_prepw(AllW aw) {
    int e = blockIdx.x * blockDim.x + threadIdx.x;
    if (e >= NLAYER * 512 * 128) return;
    int l = e >> 16;
    int r = e & 65535;
    int n = r >> 7;
    int k = r & 127;
    const float* W = aw.W[l * 4 + (n >> 7)];
    float v = W[k * 128 + (n & 127)];
    __nv_bfloat16 hi = __float2bfloat16(v);
    float resid = v - __bfloat162float(hi);
    __nv_bfloat16 lo = __float2bfloat16(resid);
    g_wtb[((size_t)(l * 2 + 0) * 512 + n) * 128 + k] = hi;
    g_wtb[((size_t)(l * 2 + 1) * 512 + n) * 128 + k] = lo;
}

// ---------------- mma.sync / ldmatrix helpers ----------------
__device__ __forceinline__ void mma16816(float* d, const uint32_t* a, const uint32_t* b) {
    asm volatile(
        "mma.sync.aligned.m16n8k16.row.col.f32.bf16.bf16.f32 "
        "{%0,%1,%2,%3}, {%4,%5,%6,%7}, {%8,%9}, {%0,%1,%2,%3};"
        : "+f"(d[0]), "+f"(d[1]), "+f"(d[2]), "+f"(d[3])
        : "r"(a[0]), "r"(a[1]), "r"(a[2]), "r"(a[3]), "r"(b[0]), "r"(b[1]));
}

__device__ __forceinline__ void ldsm_x4(uint32_t& r0, uint32_t& r1, uint32_t& r2, uint32_t& r3,
                                        uint32_t addr) {
    asm volatile("ldmatrix.sync.aligned.m8n8.x4.shared.b16 {%0,%1,%2,%3}, [%4];"
        : "=r"(r0), "=r"(r1), "=r"(r2), "=r"(r3) : "r"(addr));
}

__device__ __forceinline__ uint32_t smem_u32(const void* p) {
    uint32_t a;
    asm("{ .reg .u64 t; cvta.to.shared.u64 t, %1; cvt.u32.u64 %0, t; }" : "=r"(a) : "l"(p));
    return a;
}

// ---------------- tensor-core QKVS GEMM via mma.sync (split-bf16) ----------------
// C[NPAD,512] = A[NPAD,128] @ Wconcat + b.  D = Ah*Bh + Ah*Bl + Al*Bh, fp32 accum.
// grid (NPAD/128, 4). 8 warps, warp tile 64x32. Fragment loads via ldmatrix.x4
// (12 LDSM per k16 step instead of 48 LDS.32 -> relieve the L1/LSU bound ncu showed).
#define SSTR 40    // smem row stride in halves (80B: bank stride 20 -> LDSM conflict-free)

__global__ void __launch_bounds__(256, 2) k_gemm_mma(AllW aw, int l, int cur) {
    __shared__ __align__(16) ushort sA[2][128][SSTR];
    __shared__ __align__(16) ushort sB[2][128][SSTR];
    __shared__ float bias_s[128];

    const int tid = threadIdx.x;
    const int wid = tid >> 5, lane = tid & 31;
    const int g = lane >> 2, t2 = (lane & 3) * 2;
    const int warpRow = wid & 1, warpCol = wid >> 1;
    const int rowBase = blockIdx.x * 128;
    const int by = blockIdx.y;
    const float* __restrict__ A = cur ? g_h1 : g_h0;
    const __nv_bfloat16* __restrict__ wtH = g_wtb + ((size_t)(l * 2 + 0) * 512 + by * 128) * 128;
    const __nv_bfloat16* __restrict__ wtL = g_wtb + ((size_t)(l * 2 + 1) * 512 + by * 128) * 128;

    if (tid < 128) bias_s[tid] = aw.b[l * 4 + by][tid];

    // per-lane ldmatrix row/col-half components (quad mapping):
    // q = lane>>3; row += (q&1)*8; colhalf += (q>>1)*8
    const int lquad = lane >> 3;
    const int l7 = lane & 7;
    const int arow_l = (lquad & 1) * 8 + l7;       // A: row offset within 16
    const int acol_l = (lquad >> 1) * 8;           // A: col-half offset (0 or 8)
    const int bq_hi = (lquad >> 1) * 8;            // B: n-row +8 selects second nt
    const int bq_k  = (lquad & 1) * 8;             // B: k-half offset

    float acc[4][4][4];
#pragma unroll
    for (int mt = 0; mt < 4; ++mt)
#pragma unroll
        for (int nt = 0; nt < 4; ++nt)
#pragma unroll
            for (int j = 0; j < 4; ++j) acc[mt][nt][j] = 0.f;

    for (int kc = 0; kc < 4; ++kc) {          // K chunks of 32
        const int k0 = kc * 32;
        // stage A chunk: 128 rows x 32 k (fp32 -> split bf16)
#pragma unroll
        for (int it = 0; it < 4; ++it) {
            int idx = tid + it * 256;
            int row = idx >> 3, q = idx & 7;
            float4 v = *reinterpret_cast<const float4*>(
                A + (size_t)(rowBase + row) * 128 + k0 + q * 4);
            __nv_bfloat16 h0 = __float2bfloat16(v.x), h1 = __float2bfloat16(v.y);
            __nv_bfloat16 h2 = __float2bfloat16(v.z), h3 = __float2bfloat16(v.w);
            __nv_bfloat16 l0 = __float2bfloat16(v.x - __bfloat162float(h0));
            __nv_bfloat16 l1 = __float2bfloat16(v.y - __bfloat162float(h1));
            __nv_bfloat16 l2 = __float2bfloat16(v.z - __bfloat162float(h2));
            __nv_bfloat16 l3 = __float2bfloat16(v.w - __bfloat162float(h3));
            uint2 hp = make_uint2(
                (uint32_t)__bfloat16_as_ushort(h0) | ((uint32_t)__bfloat16_as_ushort(h1) << 16),
                (uint32_t)__bfloat16_as_ushort(h2) | ((uint32_t)__bfloat16_as_ushort(h3) << 16));
            uint2 lp = make_uint2(
                (uint32_t)__bfloat16_as_ushort(l0) | ((uint32_t)__bfloat16_as_ushort(l1) << 16),
                (uint32_t)__bfloat16_as_ushort(l2) | ((uint32_t)__bfloat16_as_ushort(l3) << 16));
            *reinterpret_cast<uint2*>(&sA[0][row][q * 4]) = hp;
            *reinterpret_cast<uint2*>(&sA[1][row][q * 4]) = lp;
        }
        // stage B chunk: 128 n x 32 k (already split bf16 in global)
#pragma unroll
        for (int it = 0; it < 4; ++it) {
            int idx = tid + it * 256;
            int n = idx >> 3, q = idx & 7;
            uint2 hv = *reinterpret_cast<const uint2*>(wtH + (size_t)n * 128 + k0 + q * 4);
            uint2 lv = *reinterpret_cast<const uint2*>(wtL + (size_t)n * 128 + k0 + q * 4);
            *reinterpret_cast<uint2*>(&sB[0][n][q * 4]) = hv;
            *reinterpret_cast<uint2*>(&sB[1][n][q * 4]) = lv;
        }
        __syncthreads();

#pragma unroll
        for (int ks = 0; ks < 2; ++ks) {       // two k16 steps per chunk
            const int ko = ks * 16;
            // A fragments via ldmatrix.x4 (hi+lo, 4 mt tiles each)
            uint32_t ah[4][4], al[4][4];
#pragma unroll
            for (int mt = 0; mt < 4; ++mt) {
                int row = warpRow * 64 + mt * 16 + arow_l;
                uint32_t a_hi = smem_u32(&sA[0][row][ko + acol_l]);
                uint32_t a_lo = smem_u32(&sA[1][row][ko + acol_l]);
                ldsm_x4(ah[mt][0], ah[mt][1], ah[mt][2], ah[mt][3], a_hi);
                ldsm_x4(al[mt][0], al[mt][1], al[mt][2], al[mt][3], a_lo);
            }
            // B fragments via ldmatrix.x4: one load covers two nt tiles
            uint32_t bh[4][2], bl[4][2];
#pragma unroll
            for (int np = 0; np < 2; ++np) {   // nt pairs (0,1) and (2,3)
                int nrow = warpCol * 32 + np * 16 + bq_hi + l7;
                uint32_t b_hi = smem_u32(&sB[0][nrow][ko + bq_k]);
                uint32_t b_lo = smem_u32(&sB[1][nrow][ko + bq_k]);
                ldsm_x4(bh[np * 2][0], bh[np * 2][1], bh[np * 2 + 1][0], bh[np * 2 + 1][1], b_hi);
                ldsm_x4(bl[np * 2][0], bl[np * 2][1], bl[np * 2 + 1][0], bl[np * 2 + 1][1], b_lo);
            }
#pragma unroll
            for (int nt = 0; nt < 4; ++nt) {
#pragma unroll
                for (int mt = 0; mt < 4; ++mt) {
                    mma16816(acc[mt][nt], ah[mt], bh[nt]);
                    mma16816(acc[mt][nt], ah[mt], bl[nt]);
                    mma16816(acc[mt][nt], al[mt], bh[nt]);
                }
            }
        }
        __syncthreads();
    }

    // epilogue: bias add. Slabs 0,3 -> fp32 g_qkvs. Slabs 1,2 -> bf16 g_kv ONLY.
    const bool is_kv = (by == 1) || (by == 2);
    const int kvoff = (by - 1) * 128;
#pragma unroll
    for (int mt = 0; mt < 4; ++mt) {
#pragma unroll
        for (int nt = 0; nt < 4; ++nt) {
            int lc = warpCol * 32 + nt * 8 + t2;
            int r0 = rowBase + warpRow * 64 + mt * 16 + g;
            float2 b2 = make_float2(bias_s[lc], bias_s[lc + 1]);
            float2 o0 = make_float2(acc[mt][nt][0] + b2.x, acc[mt][nt][1] + b2.y);
            float2 o1 = make_float2(acc[mt][nt][2] + b2.x, acc[mt][nt][3] + b2.y);
            if (is_kv) {
                __nv_bfloat162 q0 = __floats2bfloat162_rn(o0.x, o0.y);
                __nv_bfloat162 q1 = __floats2bfloat162_rn(o1.x, o1.y);
                *reinterpret_cast<__nv_bfloat162*>(&g_kv[(size_t)r0 * 256 + kvoff + lc]) = q0;
                *reinterpret_cast<__nv_bfloat162*>(&g_kv[(size_t)(r0 + 8) * 256 + kvoff + lc]) = q1;
            } else {
                float* p0 = g_qkvs + (size_t)r0 * 512 + by * 128 + lc;
                float* p1 = g_qkvs + (size_t)(r0 + 8) * 512 + by * 128 + lc;
                *reinterpret_cast<float2*>(p0) = o0;
                *reinterpret_cast<float2*>(p1) = o1;
            }
        }
    }
}

// ---------------- attention + beta gate + relu: one warp per dst node ----------------
__global__ void __launch_bounds__(256) k_attn(const float* __restrict__ Wbeta, int cur) {
    const int warp = blockIdx.x * 8 + (threadIdx.x >> 5);
    if (warp >= NN) return;
    const int lane = threadIdx.x & 31;
    const float* __restrict__ qkvs = g_qkvs;
    const __nv_bfloat16* __restrict__ kvb = g_kv;
    float* __restrict__ hout = cur ? g_h0 : g_h1;

    const size_t base = (size_t)warp * 512;
    const float4 qv = *reinterpret_cast<const float4*>(qkvs + base + lane * 4);

    const int s0 = g_rowptr[warp];
    const int s1 = g_rowptr[warp + 1];

    float mh = -INFINITY;
    float denom = 0.f;
    float4 acc = make_float4(0.f, 0.f, 0.f, 0.f);

    for (int j = s0; j < s1; ++j) {
        int s = __ldg(&g_src[j]);
        const __nv_bfloat16* kp = kvb + (size_t)s * 256;
        uint2 kraw = *reinterpret_cast<const uint2*>(kp + lane * 4);
        uint2 vraw = *reinterpret_cast<const uint2*>(kp + 128 + lane * 4);
        float2 k01 = __bfloat1622float2(*reinterpret_cast<__nv_bfloat162*>(&kraw.x));
        float2 k23 = __bfloat1622float2(*reinterpret_cast<__nv_bfloat162*>(&kraw.y));
        float2 v01 = __bfloat1622float2(*reinterpret_cast<__nv_bfloat162*>(&vraw.x));
        float2 v23 = __bfloat1622float2(*reinterpret_cast<__nv_bfloat162*>(&vraw.y));
        float p = qv.x * k01.x + qv.y * k01.y + qv.z * k23.x + qv.w * k23.y;
        p += __shfl_xor_sync(0xffffffffu, p, 1);
        p += __shfl_xor_sync(0xffffffffu, p, 2);
        p += __shfl_xor_sync(0xffffffffu, p, 4);
        float alpha = p * 0.17677669529663687f;
        float mnew = fmaxf(mh, alpha);
        float scale = __expf(mh - mnew);
        float e = __expf(alpha - mnew);
        denom = denom * scale + e;
        acc.x = acc.x * scale + e * v01.x;
        acc.y = acc.y * scale + e * v01.y;
        acc.z = acc.z * scale + e * v23.x;
        acc.w = acc.w * scale + e * v23.y;
        mh = mnew;
    }

    float inv = 1.f / (denom + 1e-16f);
    float4 o = make_float4(acc.x * inv, acc.y * inv, acc.z * inv, acc.w * inv);
    float4 xr = *reinterpret_cast<const float4*>(qkvs + base + 384 + lane * 4);

    const int c = lane * 4;
    float bs = o.x * Wbeta[c] + o.y * Wbeta[c + 1] + o.z * Wbeta[c + 2] + o.w * Wbeta[c + 3]
             + xr.x * Wbeta[128 + c] + xr.y * Wbeta[128 + c + 1] + xr.z * Wbeta[128 + c + 2] + xr.w * Wbeta[128 + c + 3]
             + (o.x - xr.x) * Wbeta[256 + c] + (o.y - xr.y) * Wbeta[256 + c + 1]
             + (o.z - xr.z) * Wbeta[256 + c + 2] + (o.w - xr.w) * Wbeta[256 + c + 3];
#pragma unroll
    for (int off = 16; off; off >>= 1) bs += __shfl_xor_sync(0xffffffffu, bs, off);
    float beta = 1.f / (1.f + __expf(-bs));

    float4 r;
    r.x = fmaxf(beta * xr.x + (1.f - beta) * o.x, 0.f);
    r.y = fmaxf(beta * xr.y + (1.f - beta) * o.y, 0.f);
    r.z = fmaxf(beta * xr.z + (1.f - beta) * o.z, 0.f);
    r.w = fmaxf(beta * xr.w + (1.f - beta) * o.w, 0.f);
    *reinterpret_cast<float4*>(hout + (size_t)warp * 128 + c) = r;
}

// ---------------- mean pool (atomic) ----------------
__global__ void k_pool(const int* __restrict__ batch, int cur) {
    int idx = blockIdx.x * blockDim.x + threadIdx.x;
    if (idx >= NN * 32) return;
    int n = idx >> 5;
    int c4 = (idx & 31) * 4;
    const float* __restrict__ h = cur ? g_h1 : g_h0;
    int b = batch[n];
    float4 v = *reinterpret_cast<const float4*>(h + (size_t)n * 128 + c4);
    atomicAdd(&g_pool[b * 128 + c4 + 0], v.x);
    atomicAdd(&g_pool[b * 128 + c4 + 1], v.y);
    atomicAdd(&g_pool[b * 128 + c4 + 2], v.z);
    atomicAdd(&g_pool[b * 128 + c4 + 3], v.w);
    if (c4 == 0) atomicAdd(&g_cnt[b], 1.f);
}

// ---------------- per-graph MLP head ----------------
__global__ void __launch_bounds__(128) k_mlp(
    const float* __restrict__ W1, const float* __restrict__ b1,
    const float* __restrict__ W2, const float* __restrict__ b2,
    const float* __restrict__ W3, const float* __restrict__ b3,
    float* __restrict__ out)
{
    int b = blockIdx.x;
    int t = threadIdx.x;
    __shared__ float sg[128];
    __shared__ float h1[64];
    __shared__ float h2[32];
    float cnt = fmaxf(g_cnt[b], 1.f);
    sg[t] = g_pool[b * 128 + t] / cnt;
    __syncthreads();
    if (t < 64) {
        float a = b1[t];
#pragma unroll 4
        for (int i = 0; i < 128; ++i) a = fmaf(sg[i], W1[i * 64 + t], a);
        h1[t] = fmaxf(a, 0.f);
    }
    __syncthreads();
    if (t < 32) {
        float a = b2[t];
#pragma unroll 4
        for (int i = 0; i < 64; ++i) a = fmaf(h1[i], W2[i * 32 + t], a);
        h2[t] = fmaxf(a, 0.f);
    }
    __syncthreads();
    if (t == 0) {
        float a = b3[0];
#pragma unroll
        for (int i = 0; i < 32; ++i) a = fmaf(h2[i], W3[i], a);
        out[b] = 1.f / (1.f + expf(-a));
    }
}

// ---------------- launch ----------------
extern "C" void kernel_launch(void* const* d_in, const int* in_sizes, int n_in,
                              void* d_out, int out_size) {
    (void)in_sizes; (void)n_in;
    const float* x      = (const float*)d_in[0];
    const int*   ei     = (const int*)d_in[1];
    const int*   batch  = (const int*)d_in[2];

    AllW aw;
    aw.W[0] = (const float*)d_in[3];  aw.b[0] = (const float*)d_in[4];
    aw.W[1] = (const float*)d_in[5];  aw.b[1] = (const float*)d_in[6];
    aw.W[2] = (const float*)d_in[7];  aw.b[2] = (const float*)d_in[8];
    aw.W[3] = (const float*)d_in[9];  aw.b[3] = (const float*)d_in[10];
    const float* wbeta[NLAYER];
    wbeta[0] = (const float*)d_in[11];
    const float* bWq = (const float*)d_in[12]; const float* bbq = (const float*)d_in[13];
    const float* bWk = (const float*)d_in[14]; const float* bbk = (const float*)d_in[15];
    const float* bWv = (const float*)d_in[16]; const float* bbv = (const float*)d_in[17];
    const float* bWs = (const float*)d_in[18]; const float* bbs = (const float*)d_in[19];
    const float* bWb = (const float*)d_in[20];
    for (int l = 0; l < 3; ++l) {
        aw.W[(l + 1) * 4 + 0] = bWq + (size_t)l * 128 * 128;  aw.b[(l + 1) * 4 + 0] = bbq + l * 128;
        aw.W[(l + 1) * 4 + 1] = bWk + (size_t)l * 128 * 128;  aw.b[(l + 1) * 4 + 1] = bbk + l * 128;
        aw.W[(l + 1) * 4 + 2] = bWv + (size_t)l * 128 * 128;  aw.b[(l + 1) * 4 + 2] = bbv + l * 128;
        aw.W[(l + 1) * 4 + 3] = bWs + (size_t)l * 128 * 128;  aw.b[(l + 1) * 4 + 3] = bbs + l * 128;
        wbeta[l + 1] = bWb + l * 384;
    }
    const float* W1 = (const float*)d_in[21]; const float* b1 = (const float*)d_in[22];
    const float* W2 = (const float*)d_in[23]; const float* b2 = (const float*)d_in[24];
    const float* W3 = (const float*)d_in[25]; const float* b3 = (const float*)d_in[26];
    float* out = (float*)d_out;
    (void)out_size;

    dim3 gemmGrid(NPAD / 128, 4);

    // --- setup, ordered so the 4th launch (ncu's profiled slot) is gemm layer 0 ---
    k_zero<<<(GG * 128 + 255) / 256, 256>>>();                  // 1
    k_copy_x<<<(NN * 32 + 255) / 256, 256>>>(x);                // 2
    k_prepw<<<(NLAYER * 512 * 128 + 255) / 256, 256>>>(aw);     // 3
    k_gemm_mma<<<gemmGrid, 256>>>(aw, 0, 0);                    // 4  <- profiled
    k_count<<<(EE + 255) / 256, 256>>>(ei);                     // 5
    k_scan<<<1, 1024>>>();                                      // 6
    k_scatter<<<(EE + 255) / 256, 256>>>(ei);                   // 7

    // --- 4 transformer conv layers (layer-0 GEMM already issued above) ---
    int cur = 0;
    for (int l = 0; l < NLAYER; ++l) {
        if (l > 0) k_gemm_mma<<<gemmGrid, 256>>>(aw, l, cur);
        k_attn<<<(NN + 7) / 8, 256>>>(wbeta[l], cur);
        cur ^= 1;
    }

    // --- pool + MLP head ---
    k_pool<<<(NN * 32 + 255) / 256, 256>>>(batch, cur);
    k_mlp<<<GG, 128>>>(W1, b1, W2, b2, W3, b3, out);
}

// round 13
// speedup vs baseline: 1.0062x; 1.0062x over previous
#include <cuda_runtime.h>
#include <cuda_bf16.h>
#include <math.h>
#include <stdint.h>

// ---------------- problem constants ----------------
#define NN      100000      // nodes
#define NPAD    100096      // padded to 782*128
#define EE      1600000     // edges
#define GG      4096        // graphs
#define NLAYER  4           // 1 input conv + 3 blocks

// ---------------- static scratch (no allocations allowed) ----------------
__device__ float g_h0[(size_t)NPAD * 128];      // ping
__device__ float g_h1[(size_t)NPAD * 128];      // pong
__device__ float g_qkvs[(size_t)NPAD * 512];    // [q|..|..|s] per node (fp32; k/v cols dead)
__device__ __nv_bfloat16 g_kv[(size_t)NPAD * 256]; // packed [k(128)|v(128)] bf16 per node
__device__ int   g_deg[NN];
__device__ int   g_rowptr[NN + 1];
__device__ int   g_cursor[NN];
__device__ int   g_src[EE];                     // src node per CSR slot (sorted by dst)
__device__ float g_pool[GG * 128];
__device__ float g_cnt[GG];
// split-bf16 weights: [layer][hi|lo][512 n][128 k] halves  (n-major, k-contiguous)
__device__ __nv_bfloat16 g_wtb[(size_t)NLAYER * 2 * 512 * 128];

struct AllW {
    const float* W[16];   // [layer*4 + {q,k,v,s}] each 128x128 row-major (in,out)
    const float* b[16];
};

// ---------------- utility kernels ----------------
__global__ void k_zero() {
    int i = blockIdx.x * blockDim.x + threadIdx.x;
    if (i < NN) g_deg[i] = 0;
    if (i < GG * 128) g_pool[i] = 0.f;
    if (i < GG) g_cnt[i] = 0.f;
}

__global__ void k_copy_x(const float* __restrict__ x) {
    int i = blockIdx.x * blockDim.x + threadIdx.x;   // float4 index
    if (i < NN * 32) {
        reinterpret_cast<float4*>(g_h0)[i] = reinterpret_cast<const float4*>(x)[i];
    }
}

__global__ void k_count(const int* __restrict__ ei) {
    int e = blockIdx.x * blockDim.x + threadIdx.x;
    if (e < EE) atomicAdd(&g_deg[ei[EE + e]], 1);
}

__global__ void k_scan() {
    __shared__ int ssum[1024];
    int t = threadIdx.x;
    const int per = (NN + 1023) >> 10;
    int lo = t * per;
    int hi = lo + per; if (hi > NN) hi = NN;
    if (lo > NN) lo = NN;
    int s = 0;
    for (int i = lo; i < hi; ++i) s += g_deg[i];
    ssum[t] = s;
    __syncthreads();
    for (int off = 1; off < 1024; off <<= 1) {
        int v = (t >= off) ? ssum[t - off] : 0;
        __syncthreads();
        ssum[t] += v;
        __syncthreads();
    }
    int run = (t == 0) ? 0 : ssum[t - 1];
    for (int i = lo; i < hi; ++i) {
        g_rowptr[i] = run;
        g_cursor[i] = run;
        run += g_deg[i];
    }
    if (t == 1023) g_rowptr[NN] = run;
}

__global__ void k_scatter(const int* __restrict__ ei) {
    int e = blockIdx.x * blockDim.x + threadIdx.x;
    if (e < EE) {
        int s = ei[e];
        int d = ei[EE + e];
        int slot = atomicAdd(&g_cursor[d], 1);
        g_src[slot] = s;
    }
}

// ---------------- weight prepass: transpose + split-bf16 ----------------
__global__ void k_prepw(AllW aw) {
    int e = blockIdx.x * blockDim.x + threadIdx.x;
    if (e >= NLAYER * 512 * 128) return;
    int l = e >> 16;
    int r = e & 65535;
    int n = r >> 7;
    int k = r & 127;
    const float* W = aw.W[l * 4 + (n >> 7)];
    float v = W[k * 128 + (n & 127)];
    __nv_bfloat16 hi = __float2bfloat16(v);
    float resid = v - __bfloat162float(hi);
    __nv_bfloat16 lo = __float2bfloat16(resid);
    g_wtb[((size_t)(l * 2 + 0) * 512 + n) * 128 + k] = hi;
    g_wtb[((size_t)(l * 2 + 1) * 512 + n) * 128 + k] = lo;
}

// ---------------- mma.sync / ldmatrix helpers ----------------
__device__ __forceinline__ void mma16816(float* d, const uint32_t* a, const uint32_t* b) {
    asm volatile(
        "mma.sync.aligned.m16n8k16.row.col.f32.bf16.bf16.f32 "
        "{%0,%1,%2,%3}, {%4,%5,%6,%7}, {%8,%9}, {%0,%1,%2,%3};"
        : "+f"(d[0]), "+f"(d[1]), "+f"(d[2]), "+f"(d[3])
        : "r"(a[0]), "r"(a[1]), "r"(a[2]), "r"(a[3]), "r"(b[0]), "r"(b[1]));
}

__device__ __forceinline__ void ldsm_x4(uint32_t& r0, uint32_t& r1, uint32_t& r2, uint32_t& r3,
                                        uint32_t addr) {
    asm volatile("ldmatrix.sync.aligned.m8n8.x4.shared.b16 {%0,%1,%2,%3}, [%4];"
        : "=r"(r0), "=r"(r1), "=r"(r2), "=r"(r3) : "r"(addr));
}

__device__ __forceinline__ uint32_t smem_u32(const void* p) {
    uint32_t a;
    asm("{ .reg .u64 t; cvta.to.shared.u64 t, %1; cvt.u32.u64 %0, t; }" : "=r"(a) : "l"(p));
    return a;
}

// ---------------- tensor-core QKVS GEMM via mma.sync (split-bf16) ----------------
// C[NPAD,512] = A[NPAD,128] @ Wconcat + b.  D = Ah*Bh + Ah*Bl + Al*Bh, fp32 accum.
// grid (NPAD/128, 4). 8 warps, warp tile 64x32. Fragment loads via ldmatrix.x4
// (12 LDSM per k16 step instead of 48 LDS.32 -> relieve the L1/LSU bound ncu showed).
#define SSTR 40    // smem row stride in halves (80B: bank stride 20 -> LDSM conflict-free)

__global__ void __launch_bounds__(256, 2) k_gemm_mma(AllW aw, int l, int cur) {
    __shared__ __align__(16) ushort sA[2][128][SSTR];
    __shared__ __align__(16) ushort sB[2][128][SSTR];
    __shared__ float bias_s[128];

    const int tid = threadIdx.x;
    const int wid = tid >> 5, lane = tid & 31;
    const int g = lane >> 2, t2 = (lane & 3) * 2;
    const int warpRow = wid & 1, warpCol = wid >> 1;
    const int rowBase = blockIdx.x * 128;
    const int by = blockIdx.y;
    const float* __restrict__ A = cur ? g_h1 : g_h0;
    const __nv_bfloat16* __restrict__ wtH = g_wtb + ((size_t)(l * 2 + 0) * 512 + by * 128) * 128;
    const __nv_bfloat16* __restrict__ wtL = g_wtb + ((size_t)(l * 2 + 1) * 512 + by * 128) * 128;

    if (tid < 128) bias_s[tid] = aw.b[l * 4 + by][tid];

    // per-lane ldmatrix row/col-half components (quad mapping):
    // q = lane>>3; row += (q&1)*8; colhalf += (q>>1)*8
    const int lquad = lane >> 3;
    const int l7 = lane & 7;
    const int arow_l = (lquad & 1) * 8 + l7;       // A: row offset within 16
    const int acol_l = (lquad >> 1) * 8;           // A: col-half offset (0 or 8)
    const int bq_hi = (lquad >> 1) * 8;            // B: n-row +8 selects second nt
    const int bq_k  = (lquad & 1) * 8;             // B: k-half offset

    float acc[4][4][4];
#pragma unroll
    for (int mt = 0; mt < 4; ++mt)
#pragma unroll
        for (int nt = 0; nt < 4; ++nt)
#pragma unroll
            for (int j = 0; j < 4; ++j) acc[mt][nt][j] = 0.f;

    for (int kc = 0; kc < 4; ++kc) {          // K chunks of 32
        const int k0 = kc * 32;
        // stage A chunk: 128 rows x 32 k (fp32 -> split bf16)
#pragma unroll
        for (int it = 0; it < 4; ++it) {
            int idx = tid + it * 256;
            int row = idx >> 3, q = idx & 7;
            float4 v = *reinterpret_cast<const float4*>(
                A + (size_t)(rowBase + row) * 128 + k0 + q * 4);
            __nv_bfloat16 h0 = __float2bfloat16(v.x), h1 = __float2bfloat16(v.y);
            __nv_bfloat16 h2 = __float2bfloat16(v.z), h3 = __float2bfloat16(v.w);
            __nv_bfloat16 l0 = __float2bfloat16(v.x - __bfloat162float(h0));
            __nv_bfloat16 l1 = __float2bfloat16(v.y - __bfloat162float(h1));
            __nv_bfloat16 l2 = __float2bfloat16(v.z - __bfloat162float(h2));
            __nv_bfloat16 l3 = __float2bfloat16(v.w - __bfloat162float(h3));
            uint2 hp = make_uint2(
                (uint32_t)__bfloat16_as_ushort(h0) | ((uint32_t)__bfloat16_as_ushort(h1) << 16),
                (uint32_t)__bfloat16_as_ushort(h2) | ((uint32_t)__bfloat16_as_ushort(h3) << 16));
            uint2 lp = make_uint2(
                (uint32_t)__bfloat16_as_ushort(l0) | ((uint32_t)__bfloat16_as_ushort(l1) << 16),
                (uint32_t)__bfloat16_as_ushort(l2) | ((uint32_t)__bfloat16_as_ushort(l3) << 16));
            *reinterpret_cast<uint2*>(&sA[0][row][q * 4]) = hp;
            *reinterpret_cast<uint2*>(&sA[1][row][q * 4]) = lp;
        }
        // stage B chunk: 128 n x 32 k (already split bf16 in global)
#pragma unroll
        for (int it = 0; it < 4; ++it) {
            int idx = tid + it * 256;
            int n = idx >> 3, q = idx & 7;
            uint2 hv = *reinterpret_cast<const uint2*>(wtH + (size_t)n * 128 + k0 + q * 4);
            uint2 lv = *reinterpret_cast<const uint2*>(wtL + (size_t)n * 128 + k0 + q * 4);
            *reinterpret_cast<uint2*>(&sB[0][n][q * 4]) = hv;
            *reinterpret_cast<uint2*>(&sB[1][n][q * 4]) = lv;
        }
        __syncthreads();

#pragma unroll
        for (int ks = 0; ks < 2; ++ks) {       // two k16 steps per chunk
            const int ko = ks * 16;
            // A fragments via ldmatrix.x4 (hi+lo, 4 mt tiles each)
            uint32_t ah[4][4], al[4][4];
#pragma unroll
            for (int mt = 0; mt < 4; ++mt) {
                int row = warpRow * 64 + mt * 16 + arow_l;
                uint32_t a_hi = smem_u32(&sA[0][row][ko + acol_l]);
                uint32_t a_lo = smem_u32(&sA[1][row][ko + acol_l]);
                ldsm_x4(ah[mt][0], ah[mt][1], ah[mt][2], ah[mt][3], a_hi);
                ldsm_x4(al[mt][0], al[mt][1], al[mt][2], al[mt][3], a_lo);
            }
            // B fragments via ldmatrix.x4: one load covers two nt tiles
            uint32_t bh[4][2], bl[4][2];
#pragma unroll
            for (int np = 0; np < 2; ++np) {   // nt pairs (0,1) and (2,3)
                int nrow = warpCol * 32 + np * 16 + bq_hi + l7;
                uint32_t b_hi = smem_u32(&sB[0][nrow][ko + bq_k]);
                uint32_t b_lo = smem_u32(&sB[1][nrow][ko + bq_k]);
                ldsm_x4(bh[np * 2][0], bh[np * 2][1], bh[np * 2 + 1][0], bh[np * 2 + 1][1], b_hi);
                ldsm_x4(bl[np * 2][0], bl[np * 2][1], bl[np * 2 + 1][0], bl[np * 2 + 1][1], b_lo);
            }
#pragma unroll
            for (int nt = 0; nt < 4; ++nt) {
#pragma unroll
                for (int mt = 0; mt < 4; ++mt) {
                    mma16816(acc[mt][nt], ah[mt], bh[nt]);
                    mma16816(acc[mt][nt], ah[mt], bl[nt]);
                    mma16816(acc[mt][nt], al[mt], bh[nt]);
                }
            }
        }
        __syncthreads();
    }

    // epilogue: bias add. Slabs 0,3 -> fp32 g_qkvs. Slabs 1,2 -> bf16 g_kv ONLY.
    const bool is_kv = (by == 1) || (by == 2);
    const int kvoff = (by - 1) * 128;
#pragma unroll
    for (int mt = 0; mt < 4; ++mt) {
#pragma unroll
        for (int nt = 0; nt < 4; ++nt) {
            int lc = warpCol * 32 + nt * 8 + t2;
            int r0 = rowBase + warpRow * 64 + mt * 16 + g;
            float2 b2 = make_float2(bias_s[lc], bias_s[lc + 1]);
            float2 o0 = make_float2(acc[mt][nt][0] + b2.x, acc[mt][nt][1] + b2.y);
            float2 o1 = make_float2(acc[mt][nt][2] + b2.x, acc[mt][nt][3] + b2.y);
            if (is_kv) {
                __nv_bfloat162 q0 = __floats2bfloat162_rn(o0.x, o0.y);
                __nv_bfloat162 q1 = __floats2bfloat162_rn(o1.x, o1.y);
                *reinterpret_cast<__nv_bfloat162*>(&g_kv[(size_t)r0 * 256 + kvoff + lc]) = q0;
                *reinterpret_cast<__nv_bfloat162*>(&g_kv[(size_t)(r0 + 8) * 256 + kvoff + lc]) = q1;
            } else {
                float* p0 = g_qkvs + (size_t)r0 * 512 + by * 128 + lc;
                float* p1 = g_qkvs + (size_t)(r0 + 8) * 512 + by * 128 + lc;
                *reinterpret_cast<float2*>(p0) = o0;
                *reinterpret_cast<float2*>(p1) = o1;
            }
        }
    }
}

// ---------------- attention + beta gate + relu: one warp per dst node ----------------
__global__ void __launch_bounds__(256) k_attn(const float* __restrict__ Wbeta, int cur) {
    const int warp = blockIdx.x * 8 + (threadIdx.x >> 5);
    if (warp >= NN) return;
    const int lane = threadIdx.x & 31;
    const float* __restrict__ qkvs = g_qkvs;
    const __nv_bfloat16* __restrict__ kvb = g_kv;
    float* __restrict__ hout = cur ? g_h0 : g_h1;

    const size_t base = (size_t)warp * 512;
    const float4 qv = *reinterpret_cast<const float4*>(qkvs + base + lane * 4);

    const int s0 = g_rowptr[warp];
    const int s1 = g_rowptr[warp + 1];

    float mh = -INFINITY;
    float denom = 0.f;
    float4 acc = make_float4(0.f, 0.f, 0.f, 0.f);

    for (int j = s0; j < s1; ++j) {
        int s = __ldg(&g_src[j]);
        const __nv_bfloat16* kp = kvb + (size_t)s * 256;
        uint2 kraw = *reinterpret_cast<const uint2*>(kp + lane * 4);
        uint2 vraw = *reinterpret_cast<const uint2*>(kp + 128 + lane * 4);
        float2 k01 = __bfloat1622float2(*reinterpret_cast<__nv_bfloat162*>(&kraw.x));
        float2 k23 = __bfloat1622float2(*reinterpret_cast<__nv_bfloat162*>(&kraw.y));
        float2 v01 = __bfloat1622float2(*reinterpret_cast<__nv_bfloat162*>(&vraw.x));
        float2 v23 = __bfloat1622float2(*reinterpret_cast<__nv_bfloat162*>(&vraw.y));
        float p = qv.x * k01.x + qv.y * k01.y + qv.z * k23.x + qv.w * k23.y;
        p += __shfl_xor_sync(0xffffffffu, p, 1);
        p += __shfl_xor_sync(0xffffffffu, p, 2);
        p += __shfl_xor_sync(0xffffffffu, p, 4);
        float alpha = p * 0.17677669529663687f;
        float mnew = fmaxf(mh, alpha);
        float scale = __expf(mh - mnew);
        float e = __expf(alpha - mnew);
        denom = denom * scale + e;
        acc.x = acc.x * scale + e * v01.x;
        acc.y = acc.y * scale + e * v01.y;
        acc.z = acc.z * scale + e * v23.x;
        acc.w = acc.w * scale + e * v23.y;
        mh = mnew;
    }

    float inv = 1.f / (denom + 1e-16f);
    float4 o = make_float4(acc.x * inv, acc.y * inv, acc.z * inv, acc.w * inv);
    float4 xr = *reinterpret_cast<const float4*>(qkvs + base + 384 + lane * 4);

    const int c = lane * 4;
    float bs = o.x * Wbeta[c] + o.y * Wbeta[c + 1] + o.z * Wbeta[c + 2] + o.w * Wbeta[c + 3]
             + xr.x * Wbeta[128 + c] + xr.y * Wbeta[128 + c + 1] + xr.z * Wbeta[128 + c + 2] + xr.w * Wbeta[128 + c + 3]
             + (o.x - xr.x) * Wbeta[256 + c] + (o.y - xr.y) * Wbeta[256 + c + 1]
             + (o.z - xr.z) * Wbeta[256 + c + 2] + (o.w - xr.w) * Wbeta[256 + c + 3];
#pragma unroll
    for (int off = 16; off; off >>= 1) bs += __shfl_xor_sync(0xffffffffu, bs, off);
    float beta = 1.f / (1.f + __expf(-bs));

    float4 r;
    r.x = fmaxf(beta * xr.x + (1.f - beta) * o.x, 0.f);
    r.y = fmaxf(beta * xr.y + (1.f - beta) * o.y, 0.f);
    r.z = fmaxf(beta * xr.z + (1.f - beta) * o.z, 0.f);
    r.w = fmaxf(beta * xr.w + (1.f - beta) * o.w, 0.f);
    *reinterpret_cast<float4*>(hout + (size_t)warp * 128 + c) = r;
}

// ---------------- mean pool (atomic) ----------------
__global__ void k_pool(const int* __restrict__ batch, int cur) {
    int idx = blockIdx.x * blockDim.x + threadIdx.x;
    if (idx >= NN * 32) return;
    int n = idx >> 5;
    int c4 = (idx & 31) * 4;
    const float* __restrict__ h = cur ? g_h1 : g_h0;
    int b = batch[n];
    float4 v = *reinterpret_cast<const float4*>(h + (size_t)n * 128 + c4);
    atomicAdd(&g_pool[b * 128 + c4 + 0], v.x);
    atomicAdd(&g_pool[b * 128 + c4 + 1], v.y);
    atomicAdd(&g_pool[b * 128 + c4 + 2], v.z);
    atomicAdd(&g_pool[b * 128 + c4 + 3], v.w);
    if (c4 == 0) atomicAdd(&g_cnt[b], 1.f);
}

// ---------------- per-graph MLP head ----------------
__global__ void __launch_bounds__(128) k_mlp(
    const float* __restrict__ W1, const float* __restrict__ b1,
    const float* __restrict__ W2, const float* __restrict__ b2,
    const float* __restrict__ W3, const float* __restrict__ b3,
    float* __restrict__ out)
{
    int b = blockIdx.x;
    int t = threadIdx.x;
    __shared__ float sg[128];
    __shared__ float h1[64];
    __shared__ float h2[32];
    float cnt = fmaxf(g_cnt[b], 1.f);
    sg[t] = g_pool[b * 128 + t] / cnt;
    __syncthreads();
    if (t < 64) {
        float a = b1[t];
#pragma unroll 4
        for (int i = 0; i < 128; ++i) a = fmaf(sg[i], W1[i * 64 + t], a);
        h1[t] = fmaxf(a, 0.f);
    }
    __syncthreads();
    if (t < 32) {
        float a = b2[t];
#pragma unroll 4
        for (int i = 0; i < 64; ++i) a = fmaf(h1[i], W2[i * 32 + t], a);
        h2[t] = fmaxf(a, 0.f);
    }
    __syncthreads();
    if (t == 0) {
        float a = b3[0];
#pragma unroll
        for (int i = 0; i < 32; ++i) a = fmaf(h2[i], W3[i], a);
        out[b] = 1.f / (1.f + expf(-a));
    }
}

// ---------------- launch ----------------
extern "C" void kernel_launch(void* const* d_in, const int* in_sizes, int n_in,
                              void* d_out, int out_size) {
    (void)in_sizes; (void)n_in;
    const float* x      = (const float*)d_in[0];
    const int*   ei     = (const int*)d_in[1];
    const int*   batch  = (const int*)d_in[2];

    AllW aw;
    aw.W[0] = (const float*)d_in[3];  aw.b[0] = (const float*)d_in[4];
    aw.W[1] = (const float*)d_in[5];  aw.b[1] = (const float*)d_in[6];
    aw.W[2] = (const float*)d_in[7];  aw.b[2] = (const float*)d_in[8];
    aw.W[3] = (const float*)d_in[9];  aw.b[3] = (const float*)d_in[10];
    const float* wbeta[NLAYER];
    wbeta[0] = (const float*)d_in[11];
    const float* bWq = (const float*)d_in[12]; const float* bbq = (const float*)d_in[13];
    const float* bWk = (const float*)d_in[14]; const float* bbk = (const float*)d_in[15];
    const float* bWv = (const float*)d_in[16]; const float* bbv = (const float*)d_in[17];
    const float* bWs = (const float*)d_in[18]; const float* bbs = (const float*)d_in[19];
    const float* bWb = (const float*)d_in[20];
    for (int l = 0; l < 3; ++l) {
        aw.W[(l + 1) * 4 + 0] = bWq + (size_t)l * 128 * 128;  aw.b[(l + 1) * 4 + 0] = bbq + l * 128;
        aw.W[(l + 1) * 4 + 1] = bWk + (size_t)l * 128 * 128;  aw.b[(l + 1) * 4 + 1] = bbk + l * 128;
        aw.W[(l + 1) * 4 + 2] = bWv + (size_t)l * 128 * 128;  aw.b[(l + 1) * 4 + 2] = bbv + l * 128;
        aw.W[(l + 1) * 4 + 3] = bWs + (size_t)l * 128 * 128;  aw.b[(l + 1) * 4 + 3] = bbs + l * 128;
        wbeta[l + 1] = bWb + l * 384;
    }
    const float* W1 = (const float*)d_in[21]; const float* b1 = (const float*)d_in[22];
    const float* W2 = (const float*)d_in[23]; const float* b2 = (const float*)d_in[24];
    const float* W3 = (const float*)d_in[25]; const float* b3 = (const float*)d_in[26];
    float* out = (float*)d_out;
    (void)out_size;

    dim3 gemmGrid(NPAD / 128, 4);

    // --- setup, ordered so the 4th launch (ncu's profiled slot) is gemm layer 0 ---
    k_zero<<<(GG * 128 + 255) / 256, 256>>>();                  // 1
    k_copy_x<<<(NN * 32 + 255) / 256, 256>>>(x);                // 2
    k_prepw<<<(NLAYER * 512 * 128 + 255) / 256, 256>>>(aw);     // 3
    k_gemm_mma<<<gemmGrid, 256>>>(aw, 0, 0);                    // 4  <- profiled
    k_count<<<(EE + 255) / 256, 256>>>(ei);                     // 5
    k_scan<<<1, 1024>>>();                                      // 6
    k_scatter<<<(EE + 255) / 256, 256>>>(ei);                   // 7

    // --- 4 transformer conv layers (layer-0 GEMM already issued above) ---
    int cur = 0;
    for (int l = 0; l < NLAYER; ++l) {
        if (l > 0) k_gemm_mma<<<gemmGrid, 256>>>(aw, l, cur);
        k_attn<<<(NN + 7) / 8, 256>>>(wbeta[l], cur);
        cur ^= 1;
    }

    // --- pool + MLP head ---
    k_pool<<<(NN * 32 + 255) / 256, 256>>>(batch, cur);
    k_mlp<<<GG, 128>>>(W1, b1, W2, b2, W3, b3, out);
}